// round 6
// baseline (speedup 1.0000x reference)
#include <cuda_runtime.h>

#define Bb 4
#define Tt 2048
#define Dd 1024
#define Hh 16
#define HSs 64
#define Mm (Bb*Tt)   // 8192

// ---------------- scratch (device globals: allocation-free) ----------------
__device__ float g_K   [Bb*Hh*Tt*HSs];  // [B,H,T,HS]
__device__ float g_V   [Bb*Hh*Tt*HSs];
__device__ float g_cat [Mm*Dd];
__device__ float g_y   [Mm*Dd];
__device__ float g_norm[Mm*Dd];
__device__ float g_h1  [Mm*Dd];
__device__ float g_z   [Mm*Dd];

// ---------------- TF32 helpers ----------------
__device__ __forceinline__ float tf32r(float x) {
    unsigned u;
    asm("cvt.rna.tf32.f32 %0, %1;" : "=r"(u) : "f"(x));
    return __uint_as_float(u);
}

__device__ __forceinline__ void mma_tf32(float* c, const unsigned* a, const unsigned* b) {
    asm volatile(
        "mma.sync.aligned.m16n8k8.row.col.f32.tf32.tf32.f32 "
        "{%0,%1,%2,%3}, {%4,%5,%6,%7}, {%8,%9}, {%0,%1,%2,%3};\n"
        : "+f"(c[0]), "+f"(c[1]), "+f"(c[2]), "+f"(c[3])
        : "r"(a[0]), "r"(a[1]), "r"(a[2]), "r"(a[3]), "r"(b[0]), "r"(b[1]));
}

// ---------------- TF32 tensor-core GEMM: 128x128x32, 256 thr, 8 warps ----------------
// A tile: permuted-k layout As[m][k'] pitch 38. Within each k-group of 8,
// position 2i holds k=i, position 2i+1 holds k=i+4 => the m16n8k8 A-fragment
// pair (k=r, k=r+4) is one aligned LDS.64.  (cols <= 31 < 38, bounds-safe)
// B tile: Bs[k][n] pitch 136 (conflict-free).
#define APITCH 38
#define BPITCH 136
#define ASZ (128*APITCH)   // 4864 floats
#define BSZ (32*BPITCH)    // 4352 floats
#define GEMM_SMEM ((2*ASZ + 2*BSZ)*4)   // 73728 bytes

template<int BLAYOUT, int EPI>
__global__ void __launch_bounds__(256, 2) tgemm_k(
    const float* __restrict__ A, const float* __restrict__ W, float* __restrict__ C,
    const float* __restrict__ bias, const float* __restrict__ add1,
    const float* __restrict__ add2)
{
    const int K = 1024, N = 1024;
    extern __shared__ float sm[];
    float* As = sm;
    float* Bs = sm + 2 * ASZ;

    const int tid = threadIdx.x;
    const int lane = tid & 31, wid = tid >> 5;
    const int bn = blockIdx.x, bm = blockIdx.y;
    const int wm = (wid >> 2) * 64;
    const int wn = (wid & 3) * 32;
    const int q = lane >> 2, r = lane & 3;

    float acc[16][4];
    #pragma unroll
    for (int i = 0; i < 16; i++)
        #pragma unroll
        for (int j = 0; j < 4; j++) acc[i][j] = 0.f;

    const float* Ab = A + (size_t)(bm * 128) * K;
    float4 pf[4];

#define LOADG_A(kt)                                                          \
    {                                                                        \
        _Pragma("unroll")                                                    \
        for (int i = 0; i < 4; i++) {                                        \
            int f = tid + i * 256; int m_ = f >> 3, c_ = f & 7;              \
            pf[i] = *(const float4*)(Ab + (size_t)m_ * K + (kt) * 32 + 4 * c_); \
        }                                                                    \
    }
#define STS_A(buf)                                                           \
    {                                                                        \
        _Pragma("unroll")                                                    \
        for (int i = 0; i < 4; i++) {                                        \
            int f = tid + i * 256; int m_ = f >> 3, c_ = f & 7;              \
            float* p = As + (buf) * ASZ + m_ * APITCH + (c_ >> 1) * 8 + (c_ & 1); \
            p[0] = tf32r(pf[i].x); p[2] = tf32r(pf[i].y);                    \
            p[4] = tf32r(pf[i].z); p[6] = tf32r(pf[i].w);                    \
        }                                                                    \
    }
#define LOADG_B(kt)                                                          \
    {                                                                        \
        _Pragma("unroll")                                                    \
        for (int i = 0; i < 4; i++) {                                        \
            int f = tid + i * 256; int k_ = f >> 5, c_ = f & 31;             \
            if (BLAYOUT == 0) {                                              \
                pf[i] = *(const float4*)(W + (size_t)((kt) * 32 + k_) * N + bn * 128 + 4 * c_); \
            } else {                                                         \
                int n_ = bn * 128 + 4 * c_; int h_ = n_ >> 6, s_ = n_ & 63;  \
                pf[i] = *(const float4*)(W + ((size_t)h_ * K + (kt) * 32 + k_) * 64 + s_); \
            }                                                                \
        }                                                                    \
    }
#define STS_B(buf)                                                           \
    {                                                                        \
        _Pragma("unroll")                                                    \
        for (int i = 0; i < 4; i++) {                                        \
            int f = tid + i * 256; int k_ = f >> 5, c_ = f & 31;             \
            float* p = Bs + (buf) * BSZ + k_ * BPITCH + 4 * c_;              \
            p[0] = tf32r(pf[i].x); p[1] = tf32r(pf[i].y);                    \
            p[2] = tf32r(pf[i].z); p[3] = tf32r(pf[i].w);                    \
        }                                                                    \
    }
#define COMPUTE_KS(buf, ks)                                                  \
    {                                                                        \
        unsigned afr[4][4], bfr[4][2];                                       \
        const float* ab = As + (buf) * ASZ + (wm + q) * APITCH + (ks) * 8 + 2 * r; \
        _Pragma("unroll")                                                    \
        for (int mt = 0; mt < 4; mt++) {                                     \
            const float* p = ab + mt * 16 * APITCH;                          \
            uint2 u0 = *(const uint2*)(p);                                   \
            uint2 u1 = *(const uint2*)(p + 8 * APITCH);                      \
            afr[mt][0] = u0.x; afr[mt][1] = u1.x;                            \
            afr[mt][2] = u0.y; afr[mt][3] = u1.y;                            \
        }                                                                    \
        const float* bb2 = Bs + (buf) * BSZ + ((ks) * 8 + r) * BPITCH + wn + q; \
        _Pragma("unroll")                                                    \
        for (int nt = 0; nt < 4; nt++) {                                     \
            bfr[nt][0] = *(const unsigned*)(bb2 + nt * 8);                   \
            bfr[nt][1] = *(const unsigned*)(bb2 + 4 * BPITCH + nt * 8);      \
        }                                                                    \
        _Pragma("unroll")                                                    \
        for (int mt = 0; mt < 4; mt++)                                       \
            _Pragma("unroll")                                                \
            for (int nt = 0; nt < 4; nt++)                                   \
                mma_tf32(acc[mt * 4 + nt], afr[mt], bfr[nt]);                \
    }

    LOADG_A(0); STS_A(0);
    LOADG_B(0); STS_B(0);
    __syncthreads();

    for (int kt = 0; kt < 32; kt++) {
        int buf = kt & 1;
        bool more = (kt < 31);
        if (more) LOADG_A(kt + 1);
        COMPUTE_KS(buf, 0);
        COMPUTE_KS(buf, 1);
        if (more) { STS_A(buf ^ 1); LOADG_B(kt + 1); }
        COMPUTE_KS(buf, 2);
        COMPUTE_KS(buf, 3);
        if (more) STS_B(buf ^ 1);
        __syncthreads();
    }

    #pragma unroll
    for (int mt = 0; mt < 4; mt++) {
        #pragma unroll
        for (int half = 0; half < 2; half++) {
            int m = bm * 128 + wm + mt * 16 + q + half * 8;
            #pragma unroll
            for (int nt = 0; nt < 4; nt++) {
                int n = bn * 128 + wn + nt * 8 + 2 * r;
                float v0 = acc[mt * 4 + nt][half * 2 + 0];
                float v1 = acc[mt * 4 + nt][half * 2 + 1];
                if (EPI == 0) {
                    int b_ = m >> 11, t_ = m & 2047, h_ = n >> 6, s_ = n & 63;
                    float2 ov = make_float2(v0, v1);
                    *(float2*)(C + ((((size_t)b_ * Hh + h_) * Tt + t_) << 6) + s_) = ov;
                } else if (EPI == 1) {
                    size_t idx = (size_t)m * Dd + n;
                    float2 a1 = *(const float2*)(add1 + idx);
                    float2 ov = make_float2(v0 + bias[n] + a1.x, v1 + bias[n + 1] + a1.y);
                    *(float2*)(C + idx) = ov;
                } else if (EPI == 2) {
                    float u0 = v0 + bias[n], u1 = v1 + bias[n + 1];
                    float2 ov = make_float2(u0 > 0.f ? u0 : 0.f, u1 > 0.f ? u1 : 0.f);
                    *(float2*)(C + (size_t)m * Dd + n) = ov;
                } else {
                    size_t idx = (size_t)m * Dd + n;
                    float2 a1 = *(const float2*)(add1 + idx);
                    float2 a2 = *(const float2*)(add2 + idx);
                    float2 ov = make_float2(v0 + bias[n] + a1.x + a2.x,
                                            v1 + bias[n + 1] + a1.y + a2.y);
                    *(float2*)(C + idx) = ov;
                }
            }
        }
    }
#undef LOADG_A
#undef STS_A
#undef LOADG_B
#undef STS_B
#undef COMPUTE_KS
}

// ---------------- TF32 tensor-core flash attention (R3 known-good) ----------------
#define QP 68
#define KP 68
#define VP 72
#define PP 68
#define ATTN_SMEM ((128*QP + 64*KP + 64*VP + 128*PP) * 4)   // 105472 B

__global__ void __launch_bounds__(256, 2) attn_k(
    const float* __restrict__ Kg, const float* __restrict__ Vg,
    float* __restrict__ cat)
{
    extern __shared__ float sm[];
    float* Qs = sm;
    float* Ks = Qs + 128 * QP;
    float* Vs = Ks + 64 * KP;
    float* Ps = Vs + 64 * VP;

    const int qi = (int)(gridDim.x - 1) - (int)blockIdx.x;
    const int h = blockIdx.y, b = blockIdx.z;
    const int tid = threadIdx.x, lane = tid & 31, w = tid >> 5;
    const int q = lane >> 2, r = lane & 3;

    const float* Kb = Kg + (((size_t)b * Hh + h) * Tt) * HSs;
    const float* Vb = Vg + (((size_t)b * Hh + h) * Tt) * HSs;
    const float scale = 9.313225746154785e-10f;  // 64^-5 = 2^-30

    #pragma unroll
    for (int i = 0; i < 8; i++) {
        int f = tid + i * 256;
        int rr = f >> 4, cc = (f & 15) << 2;
        float4 v = *(const float4*)(Kb + (size_t)(qi * 128 + rr) * 64 + cc);
        float* p = Qs + rr * QP + cc;
        p[0] = tf32r(v.x * scale); p[1] = tf32r(v.y * scale);
        p[2] = tf32r(v.z * scale); p[3] = tf32r(v.w * scale);
    }

    float m0 = -1e30f, m1 = -1e30f, l0 = 0.f, l1 = 0.f;
    float oacc[8][4];
    #pragma unroll
    for (int nt = 0; nt < 8; nt++)
        #pragma unroll
        for (int i = 0; i < 4; i++) oacc[nt][i] = 0.f;

    const int grow0 = qi * 128 + w * 16 + q;
    const int grow1 = grow0 + 8;

    const int jmax = 2 * qi + 1;
    for (int j = 0; j <= jmax; j++) {
        __syncthreads();
        #pragma unroll
        for (int i = 0; i < 4; i++) {
            int f = tid + i * 256;
            int rr = f >> 4, cc = (f & 15) << 2;
            float4 kv = *(const float4*)(Kb + (size_t)(j * 64 + rr) * 64 + cc);
            float4 vv = *(const float4*)(Vb + (size_t)(j * 64 + rr) * 64 + cc);
            float* pk = Ks + rr * KP + cc;
            pk[0] = tf32r(kv.x); pk[1] = tf32r(kv.y);
            pk[2] = tf32r(kv.z); pk[3] = tf32r(kv.w);
            float* pv = Vs + rr * VP + cc;
            pv[0] = tf32r(vv.x); pv[1] = tf32r(vv.y);
            pv[2] = tf32r(vv.z); pv[3] = tf32r(vv.w);
        }
        __syncthreads();

        float sacc[8][4];
        #pragma unroll
        for (int nt = 0; nt < 8; nt++)
            #pragma unroll
            for (int i = 0; i < 4; i++) sacc[nt][i] = 0.f;

        #pragma unroll
        for (int ks = 0; ks < 8; ks++) {
            const float* ap = Qs + (w * 16 + q) * QP + ks * 8 + r;
            unsigned afr[4];
            afr[0] = *(const unsigned*)(ap);
            afr[1] = *(const unsigned*)(ap + 8 * QP);
            afr[2] = *(const unsigned*)(ap + 4);
            afr[3] = *(const unsigned*)(ap + 8 * QP + 4);
            #pragma unroll
            for (int nt = 0; nt < 8; nt++) {
                const float* bp = Ks + (nt * 8 + q) * KP + ks * 8 + r;
                unsigned bfr[2];
                bfr[0] = *(const unsigned*)(bp);
                bfr[1] = *(const unsigned*)(bp + 4);
                mma_tf32(sacc[nt], afr, bfr);
            }
        }

        const bool needmask = (j >= 2 * qi);
        if (needmask) {
            #pragma unroll
            for (int nt = 0; nt < 8; nt++) {
                int c0 = j * 64 + nt * 8 + 2 * r;
                if (c0 > grow0)     sacc[nt][0] = -1e30f;
                if (c0 + 1 > grow0) sacc[nt][1] = -1e30f;
                if (c0 > grow1)     sacc[nt][2] = -1e30f;
                if (c0 + 1 > grow1) sacc[nt][3] = -1e30f;
            }
        }
        float mx0 = -1e30f, mx1 = -1e30f;
        #pragma unroll
        for (int nt = 0; nt < 8; nt++) {
            mx0 = fmaxf(mx0, fmaxf(sacc[nt][0], sacc[nt][1]));
            mx1 = fmaxf(mx1, fmaxf(sacc[nt][2], sacc[nt][3]));
        }
        mx0 = fmaxf(mx0, __shfl_xor_sync(0xffffffffu, mx0, 1));
        mx0 = fmaxf(mx0, __shfl_xor_sync(0xffffffffu, mx0, 2));
        mx1 = fmaxf(mx1, __shfl_xor_sync(0xffffffffu, mx1, 1));
        mx1 = fmaxf(mx1, __shfl_xor_sync(0xffffffffu, mx1, 2));

        float mn0 = fmaxf(m0, mx0), mn1 = fmaxf(m1, mx1);
        float al0 = __expf(m0 - mn0), al1 = __expf(m1 - mn1);
        m0 = mn0; m1 = mn1;

        float rs0 = 0.f, rs1 = 0.f;
        #pragma unroll
        for (int nt = 0; nt < 8; nt++) {
            float p0 = __expf(sacc[nt][0] - mn0);
            float p1 = __expf(sacc[nt][1] - mn0);
            float p2 = __expf(sacc[nt][2] - mn1);
            float p3 = __expf(sacc[nt][3] - mn1);
            rs0 += p0 + p1; rs1 += p2 + p3;
            float* pp0 = Ps + (w * 16 + q) * PP + nt * 8 + 2 * r;
            *(float2*)pp0 = make_float2(tf32r(p0), tf32r(p1));
            *(float2*)(pp0 + 8 * PP) = make_float2(tf32r(p2), tf32r(p3));
        }
        rs0 += __shfl_xor_sync(0xffffffffu, rs0, 1);
        rs0 += __shfl_xor_sync(0xffffffffu, rs0, 2);
        rs1 += __shfl_xor_sync(0xffffffffu, rs1, 1);
        rs1 += __shfl_xor_sync(0xffffffffu, rs1, 2);
        l0 = l0 * al0 + rs0;
        l1 = l1 * al1 + rs1;
        #pragma unroll
        for (int nt = 0; nt < 8; nt++) {
            oacc[nt][0] *= al0; oacc[nt][1] *= al0;
            oacc[nt][2] *= al1; oacc[nt][3] *= al1;
        }
        __syncwarp();

        #pragma unroll
        for (int ks = 0; ks < 8; ks++) {
            const float* ap = Ps + (w * 16 + q) * PP + ks * 8 + r;
            unsigned afr[4];
            afr[0] = *(const unsigned*)(ap);
            afr[1] = *(const unsigned*)(ap + 8 * PP);
            afr[2] = *(const unsigned*)(ap + 4);
            afr[3] = *(const unsigned*)(ap + 8 * PP + 4);
            #pragma unroll
            for (int nt = 0; nt < 8; nt++) {
                const float* bp = Vs + (ks * 8 + r) * VP + nt * 8 + q;
                unsigned bfr[2];
                bfr[0] = *(const unsigned*)(bp);
                bfr[1] = *(const unsigned*)(bp + 4 * VP);
                mma_tf32(oacc[nt], afr, bfr);
            }
        }
    }

    float inv0 = 1.f / l0, inv1 = 1.f / l1;
    #pragma unroll
    for (int nt = 0; nt < 8; nt++) {
        float* d0 = cat + ((size_t)b * Tt + grow0) * Dd + h * 64 + nt * 8 + 2 * r;
        *(float2*)d0 = make_float2(oacc[nt][0] * inv0, oacc[nt][1] * inv0);
        float* d1 = cat + ((size_t)b * Tt + grow1) * Dd + h * 64 + nt * 8 + 2 * r;
        *(float2*)d1 = make_float2(oacc[nt][2] * inv1, oacc[nt][3] * inv1);
    }
}

// ---------------- LayerNorm: one block per row of 1024 ----------------
__global__ void __launch_bounds__(256) ln_k(
    const float* __restrict__ in, const float* __restrict__ g,
    const float* __restrict__ bb, float* __restrict__ out)
{
    __shared__ float rs[8], rq[8];
    int row = blockIdx.x;
    const float4 v = ((const float4*)(in + (size_t)row * Dd))[threadIdx.x];
    float s = v.x + v.y + v.z + v.w;
    float q = v.x * v.x + v.y * v.y + v.z * v.z + v.w * v.w;
    #pragma unroll
    for (int w = 16; w >= 1; w >>= 1) {
        s += __shfl_xor_sync(0xffffffffu, s, w);
        q += __shfl_xor_sync(0xffffffffu, q, w);
    }
    int warp = threadIdx.x >> 5, lane = threadIdx.x & 31;
    if (lane == 0) { rs[warp] = s; rq[warp] = q; }
    __syncthreads();
    if (threadIdx.x == 0) {
        float ts = 0.f, tq = 0.f;
        #pragma unroll
        for (int i = 0; i < 8; i++) { ts += rs[i]; tq += rq[i]; }
        float mean = ts * (1.f / 1024.f);
        float var  = tq * (1.f / 1024.f) - mean * mean;
        rs[0] = mean;
        rq[0] = rsqrtf(var + 1e-5f);
    }
    __syncthreads();
    float mean = rs[0], inv = rq[0];
    const float4 g4 = ((const float4*)g )[threadIdx.x];
    const float4 b4 = ((const float4*)bb)[threadIdx.x];
    float4 ov;
    ov.x = (v.x - mean) * inv * g4.x + b4.x;
    ov.y = (v.y - mean) * inv * g4.y + b4.y;
    ov.z = (v.z - mean) * inv * g4.z + b4.z;
    ov.w = (v.w - mean) * inv * g4.w + b4.w;
    ((float4*)(out + (size_t)row * Dd))[threadIdx.x] = ov;
}

// ---------------- driver ----------------
extern "C" void kernel_launch(void* const* d_in, const int* in_sizes, int n_in,
                              void* d_out, int out_size)
{
    const float* x   = (const float*)d_in[0];
    const float* Wk  = (const float*)d_in[1];
    const float* Wv  = (const float*)d_in[2];
    const float* Wo  = (const float*)d_in[3];
    const float* bo  = (const float*)d_in[4];
    const float* g1  = (const float*)d_in[5];
    const float* b1  = (const float*)d_in[6];
    const float* Wf1 = (const float*)d_in[7];
    const float* bf1 = (const float*)d_in[8];
    const float* Wf2 = (const float*)d_in[9];
    const float* bf2 = (const float*)d_in[10];
    const float* g2  = (const float*)d_in[11];
    const float* b2  = (const float*)d_in[12];
    float* out = (float*)d_out;

    float *pK, *pV, *pcat, *py, *pnorm, *ph1, *pz;
    cudaGetSymbolAddress((void**)&pK,    g_K);
    cudaGetSymbolAddress((void**)&pV,    g_V);
    cudaGetSymbolAddress((void**)&pcat,  g_cat);
    cudaGetSymbolAddress((void**)&py,    g_y);
    cudaGetSymbolAddress((void**)&pnorm, g_norm);
    cudaGetSymbolAddress((void**)&ph1,   g_h1);
    cudaGetSymbolAddress((void**)&pz,    g_z);

    cudaFuncSetAttribute(attn_k, cudaFuncAttributeMaxDynamicSharedMemorySize, ATTN_SMEM);
    cudaFuncSetAttribute(tgemm_k<1,0>, cudaFuncAttributeMaxDynamicSharedMemorySize, GEMM_SMEM);
    cudaFuncSetAttribute(tgemm_k<0,1>, cudaFuncAttributeMaxDynamicSharedMemorySize, GEMM_SMEM);
    cudaFuncSetAttribute(tgemm_k<0,2>, cudaFuncAttributeMaxDynamicSharedMemorySize, GEMM_SMEM);
    cudaFuncSetAttribute(tgemm_k<0,3>, cudaFuncAttributeMaxDynamicSharedMemorySize, GEMM_SMEM);

    dim3 gg(8, 64), tb(256);

    // 1-2: K and V projections
    tgemm_k<1, 0><<<gg, tb, GEMM_SMEM>>>(x, Wk, pK, nullptr, nullptr, nullptr);
    tgemm_k<1, 0><<<gg, tb, GEMM_SMEM>>>(x, Wv, pV, nullptr, nullptr, nullptr);

    // 3: causal flash attention (tensor cores)
    attn_k<<<dim3(Tt / 128, Hh, Bb), 256, ATTN_SMEM>>>(pK, pV, pcat);

    // 4: y = cat @ Wo + bo + x
    tgemm_k<0, 1><<<gg, tb, GEMM_SMEM>>>(pcat, Wo, py, bo, x, nullptr);

    // 5: norm = LN1(y)
    ln_k<<<Mm, 256>>>(py, g1, b1, pnorm);

    // 6: h1 = relu(norm @ Wf1 + bf1)
    tgemm_k<0, 2><<<gg, tb, GEMM_SMEM>>>(pnorm, Wf1, ph1, bf1, nullptr, nullptr);

    // 7: z = h1 @ Wf2 + bf2 + norm + x
    tgemm_k<0, 3><<<gg, tb, GEMM_SMEM>>>(ph1, Wf2, pz, bf2, pnorm, x);

    // 8: out = LN2(z)
    ln_k<<<Mm, 256>>>(pz, g2, b2, out);
}

// round 7
// speedup vs baseline: 1.2566x; 1.2566x over previous
#include <cuda_runtime.h>
#include <cstdint>

#define Bb 4
#define Tt 2048
#define Dd 1024
#define Hh 16
#define HSs 64
#define Mm (Bb*Tt)   // 8192

// ---------------- scratch (device globals: allocation-free) ----------------
__device__ float g_K   [Bb*Hh*Tt*HSs];  // [B,H,T,HS]
__device__ float g_V   [Bb*Hh*Tt*HSs];
__device__ float g_cat [Mm*Dd];
__device__ float g_y   [Mm*Dd];
__device__ float g_norm[Mm*Dd];
__device__ float g_h1  [Mm*Dd];
__device__ float g_z   [Mm*Dd];

// ---------------- helpers ----------------
__device__ __forceinline__ uint32_t smem_u32(const void* p) {
    uint32_t a;
    asm("{ .reg .u64 t; cvta.to.shared.u64 t, %1; cvt.u32.u64 %0, t; }" : "=r"(a) : "l"(p));
    return a;
}

__device__ __forceinline__ float tf32r(float x) {
    unsigned u;
    asm("cvt.rna.tf32.f32 %0, %1;" : "=r"(u) : "f"(x));
    return __uint_as_float(u);
}

__device__ __forceinline__ void mma_tf32(float* c, const unsigned* a, const unsigned* b) {
    asm volatile(
        "mma.sync.aligned.m16n8k8.row.col.f32.tf32.tf32.f32 "
        "{%0,%1,%2,%3}, {%4,%5,%6,%7}, {%8,%9}, {%0,%1,%2,%3};\n"
        : "+f"(c[0]), "+f"(c[1]), "+f"(c[2]), "+f"(c[3])
        : "r"(a[0]), "r"(a[1]), "r"(a[2]), "r"(a[3]), "r"(b[0]), "r"(b[1]));
}

// ---------------- TF32 tensor-core GEMM, cp.async pipeline ----------------
// Tile layouts identical to the measured-good R2 kernel:
//   As[m][k] pitch 36 (frag banks 4q+r: conflict-free)
//   Bs[k][n] pitch 136 (frag banks 8r+q: conflict-free)
// Global->shared via cp.async.cg (no register staging, no cvt — HMMA.TF32
// truncates fp32 mantissa in hardware).
#define APITCH 36
#define BPITCH 136
#define ASZ (128*APITCH)   // 4608 floats
#define BSZ (32*BPITCH)    // 4352 floats
#define GEMM_SMEM ((2*ASZ + 2*BSZ)*4)   // 71680 bytes

template<int BLAYOUT, int EPI>
__global__ void __launch_bounds__(256, 2) tgemm_k(
    const float* __restrict__ A, const float* __restrict__ W, float* __restrict__ C,
    const float* __restrict__ bias, const float* __restrict__ add1,
    const float* __restrict__ add2)
{
    const int K = 1024, N = 1024;
    extern __shared__ float sm[];
    const uint32_t As = smem_u32(sm);                 // bytes
    const uint32_t Bs = As + 2 * ASZ * 4;

    const int tid = threadIdx.x;
    const int lane = tid & 31, wid = tid >> 5;
    const int bn = blockIdx.x, bm = blockIdx.y;
    const int wm = (wid >> 2) * 64;
    const int wn = (wid & 3) * 32;
    const int q = lane >> 2, r = lane & 3;

    float acc[16][4];
    #pragma unroll
    for (int i = 0; i < 16; i++)
        #pragma unroll
        for (int j = 0; j < 4; j++) acc[i][j] = 0.f;

    const float* Ab = A + (size_t)(bm * 128) * K;

    // per-thread cp.async source/dest (4 chunks each for A and B)
    // A: m = f>>3, c4 = f&7  (128 rows x 8 chunks)
    // B: k = f>>5, c4 = f&31 (32 rows x 32 chunks)
    const float* a_src[4];
    const float* b_src[4];
    uint32_t a_dst[4], b_dst[4];
    #pragma unroll
    for (int i = 0; i < 4; i++) {
        int f = tid + i * 256;
        int m_ = f >> 3, ca = f & 7;
        a_src[i] = Ab + (size_t)m_ * K + 4 * ca;                  // += 32 per kt
        a_dst[i] = As + (uint32_t)(m_ * APITCH + 4 * ca) * 4;     // + buf*ASZ*4
        int k_ = f >> 5, cb = f & 31;
        if (BLAYOUT == 0) {
            b_src[i] = W + (size_t)k_ * N + bn * 128 + 4 * cb;    // += 32*N per kt
        } else {
            int n_ = bn * 128 + 4 * cb, h_ = n_ >> 6, s_ = n_ & 63;
            b_src[i] = W + ((size_t)h_ * K + k_) * 64 + s_;       // += 32*64 per kt
        }
        b_dst[i] = Bs + (uint32_t)(k_ * BPITCH + 4 * cb) * 4;
    }
    const size_t b_step = (BLAYOUT == 0) ? (size_t)32 * N : (size_t)32 * 64;

#define CPA(kt, buf)                                                         \
    {                                                                        \
        _Pragma("unroll")                                                    \
        for (int i = 0; i < 4; i++) {                                        \
            asm volatile("cp.async.cg.shared.global [%0], [%1], 16;"         \
                :: "r"(a_dst[i] + (buf) * (uint32_t)(ASZ * 4)),              \
                   "l"(a_src[i] + (size_t)(kt) * 32));                       \
            asm volatile("cp.async.cg.shared.global [%0], [%1], 16;"         \
                :: "r"(b_dst[i] + (buf) * (uint32_t)(BSZ * 4)),              \
                   "l"(b_src[i] + (size_t)(kt) * b_step));                   \
        }                                                                    \
        asm volatile("cp.async.commit_group;" ::: "memory");                 \
    }

#define COMPUTE_KS(buf, ks)                                                  \
    {                                                                        \
        unsigned afr[4][4], bfr[4][2];                                       \
        const float* ab = sm + (buf) * ASZ + (wm + q) * APITCH + (ks) * 8 + r; \
        _Pragma("unroll")                                                    \
        for (int mt = 0; mt < 4; mt++) {                                     \
            const float* p = ab + mt * 16 * APITCH;                          \
            afr[mt][0] = *(const unsigned*)(p);                              \
            afr[mt][1] = *(const unsigned*)(p + 8 * APITCH);                 \
            afr[mt][2] = *(const unsigned*)(p + 4);                          \
            afr[mt][3] = *(const unsigned*)(p + 8 * APITCH + 4);             \
        }                                                                    \
        const float* bb2 = sm + 2 * ASZ + (buf) * BSZ + ((ks) * 8 + r) * BPITCH + wn + q; \
        _Pragma("unroll")                                                    \
        for (int nt = 0; nt < 4; nt++) {                                     \
            bfr[nt][0] = *(const unsigned*)(bb2 + nt * 8);                   \
            bfr[nt][1] = *(const unsigned*)(bb2 + 4 * BPITCH + nt * 8);      \
        }                                                                    \
        _Pragma("unroll")                                                    \
        for (int mt = 0; mt < 4; mt++)                                       \
            _Pragma("unroll")                                                \
            for (int nt = 0; nt < 4; nt++)                                   \
                mma_tf32(acc[mt * 4 + nt], afr[mt], bfr[nt]);                \
    }

    CPA(0, 0);

    for (int kt = 0; kt < 32; kt++) {
        const int buf = kt & 1;
        asm volatile("cp.async.wait_group 0;" ::: "memory");
        __syncthreads();                 // stage kt visible to all warps;
                                         // also: all warps done reading buf^1
        COMPUTE_KS(buf, 0);
        COMPUTE_KS(buf, 1);
        if (kt < 31) CPA(kt + 1, buf ^ 1);
        COMPUTE_KS(buf, 2);
        COMPUTE_KS(buf, 3);
    }

    // ---- epilogue (R2, measured-good) ----
    #pragma unroll
    for (int mt = 0; mt < 4; mt++) {
        #pragma unroll
        for (int half = 0; half < 2; half++) {
            int m = bm * 128 + wm + mt * 16 + q + half * 8;
            #pragma unroll
            for (int nt = 0; nt < 4; nt++) {
                int n = bn * 128 + wn + nt * 8 + 2 * r;
                float v0 = acc[mt * 4 + nt][half * 2 + 0];
                float v1 = acc[mt * 4 + nt][half * 2 + 1];
                if (EPI == 0) {
                    int b_ = m >> 11, t_ = m & 2047, h_ = n >> 6, s_ = n & 63;
                    float2 ov = make_float2(v0, v1);
                    *(float2*)(C + ((((size_t)b_ * Hh + h_) * Tt + t_) << 6) + s_) = ov;
                } else if (EPI == 1) {
                    size_t idx = (size_t)m * Dd + n;
                    float2 a1 = *(const float2*)(add1 + idx);
                    float2 ov = make_float2(v0 + bias[n] + a1.x, v1 + bias[n + 1] + a1.y);
                    *(float2*)(C + idx) = ov;
                } else if (EPI == 2) {
                    float u0 = v0 + bias[n], u1 = v1 + bias[n + 1];
                    float2 ov = make_float2(u0 > 0.f ? u0 : 0.f, u1 > 0.f ? u1 : 0.f);
                    *(float2*)(C + (size_t)m * Dd + n) = ov;
                } else {
                    size_t idx = (size_t)m * Dd + n;
                    float2 a1 = *(const float2*)(add1 + idx);
                    float2 a2 = *(const float2*)(add2 + idx);
                    float2 ov = make_float2(v0 + bias[n] + a1.x + a2.x,
                                            v1 + bias[n + 1] + a1.y + a2.y);
                    *(float2*)(C + idx) = ov;
                }
            }
        }
    }
#undef CPA
#undef COMPUTE_KS
}

// ---------------- TF32 tensor-core flash attention (R3 known-good) ----------------
#define QP 68
#define KP 68
#define VP 72
#define PP 68
#define ATTN_SMEM ((128*QP + 64*KP + 64*VP + 128*PP) * 4)   // 105472 B

__global__ void __launch_bounds__(256, 2) attn_k(
    const float* __restrict__ Kg, const float* __restrict__ Vg,
    float* __restrict__ cat)
{
    extern __shared__ float sm[];
    float* Qs = sm;
    float* Ks = Qs + 128 * QP;
    float* Vs = Ks + 64 * KP;
    float* Ps = Vs + 64 * VP;

    const int qi = (int)(gridDim.x - 1) - (int)blockIdx.x;
    const int h = blockIdx.y, b = blockIdx.z;
    const int tid = threadIdx.x, lane = tid & 31, w = tid >> 5;
    const int q = lane >> 2, r = lane & 3;

    const float* Kb = Kg + (((size_t)b * Hh + h) * Tt) * HSs;
    const float* Vb = Vg + (((size_t)b * Hh + h) * Tt) * HSs;
    const float scale = 9.313225746154785e-10f;  // 64^-5 = 2^-30

    #pragma unroll
    for (int i = 0; i < 8; i++) {
        int f = tid + i * 256;
        int rr = f >> 4, cc = (f & 15) << 2;
        float4 v = *(const float4*)(Kb + (size_t)(qi * 128 + rr) * 64 + cc);
        float* p = Qs + rr * QP + cc;
        p[0] = tf32r(v.x * scale); p[1] = tf32r(v.y * scale);
        p[2] = tf32r(v.z * scale); p[3] = tf32r(v.w * scale);
    }

    float m0 = -1e30f, m1 = -1e30f, l0 = 0.f, l1 = 0.f;
    float oacc[8][4];
    #pragma unroll
    for (int nt = 0; nt < 8; nt++)
        #pragma unroll
        for (int i = 0; i < 4; i++) oacc[nt][i] = 0.f;

    const int grow0 = qi * 128 + w * 16 + q;
    const int grow1 = grow0 + 8;

    const int jmax = 2 * qi + 1;
    for (int j = 0; j <= jmax; j++) {
        __syncthreads();
        #pragma unroll
        for (int i = 0; i < 4; i++) {
            int f = tid + i * 256;
            int rr = f >> 4, cc = (f & 15) << 2;
            float4 kv = *(const float4*)(Kb + (size_t)(j * 64 + rr) * 64 + cc);
            float4 vv = *(const float4*)(Vb + (size_t)(j * 64 + rr) * 64 + cc);
            float* pk = Ks + rr * KP + cc;
            pk[0] = tf32r(kv.x); pk[1] = tf32r(kv.y);
            pk[2] = tf32r(kv.z); pk[3] = tf32r(kv.w);
            float* pv = Vs + rr * VP + cc;
            pv[0] = tf32r(vv.x); pv[1] = tf32r(vv.y);
            pv[2] = tf32r(vv.z); pv[3] = tf32r(vv.w);
        }
        __syncthreads();

        float sacc[8][4];
        #pragma unroll
        for (int nt = 0; nt < 8; nt++)
            #pragma unroll
            for (int i = 0; i < 4; i++) sacc[nt][i] = 0.f;

        #pragma unroll
        for (int ks = 0; ks < 8; ks++) {
            const float* ap = Qs + (w * 16 + q) * QP + ks * 8 + r;
            unsigned afr[4];
            afr[0] = *(const unsigned*)(ap);
            afr[1] = *(const unsigned*)(ap + 8 * QP);
            afr[2] = *(const unsigned*)(ap + 4);
            afr[3] = *(const unsigned*)(ap + 8 * QP + 4);
            #pragma unroll
            for (int nt = 0; nt < 8; nt++) {
                const float* bp = Ks + (nt * 8 + q) * KP + ks * 8 + r;
                unsigned bfr[2];
                bfr[0] = *(const unsigned*)(bp);
                bfr[1] = *(const unsigned*)(bp + 4);
                mma_tf32(sacc[nt], afr, bfr);
            }
        }

        const bool needmask = (j >= 2 * qi);
        if (needmask) {
            #pragma unroll
            for (int nt = 0; nt < 8; nt++) {
                int c0 = j * 64 + nt * 8 + 2 * r;
                if (c0 > grow0)     sacc[nt][0] = -1e30f;
                if (c0 + 1 > grow0) sacc[nt][1] = -1e30f;
                if (c0 > grow1)     sacc[nt][2] = -1e30f;
                if (c0 + 1 > grow1) sacc[nt][3] = -1e30f;
            }
        }
        float mx0 = -1e30f, mx1 = -1e30f;
        #pragma unroll
        for (int nt = 0; nt < 8; nt++) {
            mx0 = fmaxf(mx0, fmaxf(sacc[nt][0], sacc[nt][1]));
            mx1 = fmaxf(mx1, fmaxf(sacc[nt][2], sacc[nt][3]));
        }
        mx0 = fmaxf(mx0, __shfl_xor_sync(0xffffffffu, mx0, 1));
        mx0 = fmaxf(mx0, __shfl_xor_sync(0xffffffffu, mx0, 2));
        mx1 = fmaxf(mx1, __shfl_xor_sync(0xffffffffu, mx1, 1));
        mx1 = fmaxf(mx1, __shfl_xor_sync(0xffffffffu, mx1, 2));

        float mn0 = fmaxf(m0, mx0), mn1 = fmaxf(m1, mx1);
        float al0 = __expf(m0 - mn0), al1 = __expf(m1 - mn1);
        m0 = mn0; m1 = mn1;

        float rs0 = 0.f, rs1 = 0.f;
        #pragma unroll
        for (int nt = 0; nt < 8; nt++) {
            float p0 = __expf(sacc[nt][0] - mn0);
            float p1 = __expf(sacc[nt][1] - mn0);
            float p2 = __expf(sacc[nt][2] - mn1);
            float p3 = __expf(sacc[nt][3] - mn1);
            rs0 += p0 + p1; rs1 += p2 + p3;
            float* pp0 = Ps + (w * 16 + q) * PP + nt * 8 + 2 * r;
            *(float2*)pp0 = make_float2(tf32r(p0), tf32r(p1));
            *(float2*)(pp0 + 8 * PP) = make_float2(tf32r(p2), tf32r(p3));
        }
        rs0 += __shfl_xor_sync(0xffffffffu, rs0, 1);
        rs0 += __shfl_xor_sync(0xffffffffu, rs0, 2);
        rs1 += __shfl_xor_sync(0xffffffffu, rs1, 1);
        rs1 += __shfl_xor_sync(0xffffffffu, rs1, 2);
        l0 = l0 * al0 + rs0;
        l1 = l1 * al1 + rs1;
        #pragma unroll
        for (int nt = 0; nt < 8; nt++) {
            oacc[nt][0] *= al0; oacc[nt][1] *= al0;
            oacc[nt][2] *= al1; oacc[nt][3] *= al1;
        }
        __syncwarp();

        #pragma unroll
        for (int ks = 0; ks < 8; ks++) {
            const float* ap = Ps + (w * 16 + q) * PP + ks * 8 + r;
            unsigned afr[4];
            afr[0] = *(const unsigned*)(ap);
            afr[1] = *(const unsigned*)(ap + 8 * PP);
            afr[2] = *(const unsigned*)(ap + 4);
            afr[3] = *(const unsigned*)(ap + 8 * PP + 4);
            #pragma unroll
            for (int nt = 0; nt < 8; nt++) {
                const float* bp = Vs + (ks * 8 + r) * VP + nt * 8 + q;
                unsigned bfr[2];
                bfr[0] = *(const unsigned*)(bp);
                bfr[1] = *(const unsigned*)(bp + 4 * VP);
                mma_tf32(oacc[nt], afr, bfr);
            }
        }
    }

    float inv0 = 1.f / l0, inv1 = 1.f / l1;
    #pragma unroll
    for (int nt = 0; nt < 8; nt++) {
        float* d0 = cat + ((size_t)b * Tt + grow0) * Dd + h * 64 + nt * 8 + 2 * r;
        *(float2*)d0 = make_float2(oacc[nt][0] * inv0, oacc[nt][1] * inv0);
        float* d1 = cat + ((size_t)b * Tt + grow1) * Dd + h * 64 + nt * 8 + 2 * r;
        *(float2*)d1 = make_float2(oacc[nt][2] * inv1, oacc[nt][3] * inv1);
    }
}

// ---------------- LayerNorm: one block per row of 1024 ----------------
__global__ void __launch_bounds__(256) ln_k(
    const float* __restrict__ in, const float* __restrict__ g,
    const float* __restrict__ bb, float* __restrict__ out)
{
    __shared__ float rs[8], rq[8];
    int row = blockIdx.x;
    const float4 v = ((const float4*)(in + (size_t)row * Dd))[threadIdx.x];
    float s = v.x + v.y + v.z + v.w;
    float q = v.x * v.x + v.y * v.y + v.z * v.z + v.w * v.w;
    #pragma unroll
    for (int w = 16; w >= 1; w >>= 1) {
        s += __shfl_xor_sync(0xffffffffu, s, w);
        q += __shfl_xor_sync(0xffffffffu, q, w);
    }
    int warp = threadIdx.x >> 5, lane = threadIdx.x & 31;
    if (lane == 0) { rs[warp] = s; rq[warp] = q; }
    __syncthreads();
    if (threadIdx.x == 0) {
        float ts = 0.f, tq = 0.f;
        #pragma unroll
        for (int i = 0; i < 8; i++) { ts += rs[i]; tq += rq[i]; }
        float mean = ts * (1.f / 1024.f);
        float var  = tq * (1.f / 1024.f) - mean * mean;
        rs[0] = mean;
        rq[0] = rsqrtf(var + 1e-5f);
    }
    __syncthreads();
    float mean = rs[0], inv = rq[0];
    const float4 g4 = ((const float4*)g )[threadIdx.x];
    const float4 b4 = ((const float4*)bb)[threadIdx.x];
    float4 ov;
    ov.x = (v.x - mean) * inv * g4.x + b4.x;
    ov.y = (v.y - mean) * inv * g4.y + b4.y;
    ov.z = (v.z - mean) * inv * g4.z + b4.z;
    ov.w = (v.w - mean) * inv * g4.w + b4.w;
    ((float4*)(out + (size_t)row * Dd))[threadIdx.x] = ov;
}

// ---------------- driver ----------------
extern "C" void kernel_launch(void* const* d_in, const int* in_sizes, int n_in,
                              void* d_out, int out_size)
{
    const float* x   = (const float*)d_in[0];
    const float* Wk  = (const float*)d_in[1];
    const float* Wv  = (const float*)d_in[2];
    const float* Wo  = (const float*)d_in[3];
    const float* bo  = (const float*)d_in[4];
    const float* g1  = (const float*)d_in[5];
    const float* b1  = (const float*)d_in[6];
    const float* Wf1 = (const float*)d_in[7];
    const float* bf1 = (const float*)d_in[8];
    const float* Wf2 = (const float*)d_in[9];
    const float* bf2 = (const float*)d_in[10];
    const float* g2  = (const float*)d_in[11];
    const float* b2  = (const float*)d_in[12];
    float* out = (float*)d_out;

    float *pK, *pV, *pcat, *py, *pnorm, *ph1, *pz;
    cudaGetSymbolAddress((void**)&pK,    g_K);
    cudaGetSymbolAddress((void**)&pV,    g_V);
    cudaGetSymbolAddress((void**)&pcat,  g_cat);
    cudaGetSymbolAddress((void**)&py,    g_y);
    cudaGetSymbolAddress((void**)&pnorm, g_norm);
    cudaGetSymbolAddress((void**)&ph1,   g_h1);
    cudaGetSymbolAddress((void**)&pz,    g_z);

    cudaFuncSetAttribute(attn_k, cudaFuncAttributeMaxDynamicSharedMemorySize, ATTN_SMEM);
    cudaFuncSetAttribute(tgemm_k<1,0>, cudaFuncAttributeMaxDynamicSharedMemorySize, GEMM_SMEM);
    cudaFuncSetAttribute(tgemm_k<0,1>, cudaFuncAttributeMaxDynamicSharedMemorySize, GEMM_SMEM);
    cudaFuncSetAttribute(tgemm_k<0,2>, cudaFuncAttributeMaxDynamicSharedMemorySize, GEMM_SMEM);
    cudaFuncSetAttribute(tgemm_k<0,3>, cudaFuncAttributeMaxDynamicSharedMemorySize, GEMM_SMEM);

    dim3 gg(8, 64), tb(256);

    // 1-2: K and V projections
    tgemm_k<1, 0><<<gg, tb, GEMM_SMEM>>>(x, Wk, pK, nullptr, nullptr, nullptr);
    tgemm_k<1, 0><<<gg, tb, GEMM_SMEM>>>(x, Wv, pV, nullptr, nullptr, nullptr);

    // 3: causal flash attention (tensor cores)
    attn_k<<<dim3(Tt / 128, Hh, Bb), 256, ATTN_SMEM>>>(pK, pV, pcat);

    // 4: y = cat @ Wo + bo + x
    tgemm_k<0, 1><<<gg, tb, GEMM_SMEM>>>(pcat, Wo, py, bo, x, nullptr);

    // 5: norm = LN1(y)
    ln_k<<<Mm, 256>>>(py, g1, b1, pnorm);

    // 6: h1 = relu(norm @ Wf1 + bf1)
    tgemm_k<0, 2><<<gg, tb, GEMM_SMEM>>>(pnorm, Wf1, ph1, bf1, nullptr, nullptr);

    // 7: z = h1 @ Wf2 + bf2 + norm + x
    tgemm_k<0, 3><<<gg, tb, GEMM_SMEM>>>(ph1, Wf2, pz, bf2, pnorm, x);

    // 8: out = LN2(z)
    ln_k<<<Mm, 256>>>(pz, g2, b2, out);
}